// round 12
// baseline (speedup 1.0000x reference)
#include <cuda_runtime.h>

// Problem constants
#define T_  4
#define B_  16
#define C_  512
#define N_  1024
#define CR_ 64
#define TB_ (T_ * B_)          // 64
#define BN_EPS 1e-5f

#define NB_ 592               // persistent blocks: 4/SM x 148 SMs (<= GB300 152*4)

// Scratch (allocation-free rule: __device__ globals)
__device__ float g_gap[TB_ * C_];   // [64, 512]
__device__ float g_h1[TB_ * CR_];   // [64, 64]

// Grid barriers (generation counters survive graph replays: counts return to
// 0 each use; gens increase monotonically -> deterministic across replays).
__device__ unsigned g_bar1_count = 0;
__device__ volatile unsigned g_bar1_gen = 0;
__device__ unsigned g_bar2_count = 0;
__device__ volatile unsigned g_bar2_gen = 0;

// ---------------------------------------------------------------------------
// ONE persistent kernel: LIF+GAP (grid-stride over 8192 tiles), grid barrier,
// then the whole MLP on blocks 0..63. No second launch, no cold re-warm.
// ---------------------------------------------------------------------------
__global__ void __launch_bounds__(256, 4)
snn_persistent_kernel(const float* __restrict__ x,
                      const float* __restrict__ w1,
                      const float* __restrict__ b1,
                      const float* __restrict__ gamma1,
                      const float* __restrict__ beta1,
                      const float* __restrict__ w2,
                      const float* __restrict__ b2,
                      const float* __restrict__ gamma2,
                      const float* __restrict__ beta2,
                      float* __restrict__ g,
                      float* __restrict__ h1,
                      float* __restrict__ out) {
    const int tid  = threadIdx.x;
    const int lane = tid & 31;
    const int wid  = tid >> 5;

    __shared__ float red[8][T_];

    // ================= Phase A: LIF + GAP, grid-stride ======================
    const size_t strideT = (size_t)B_ * C_ * N_;
    for (int tile = blockIdx.x; tile < B_ * C_; tile += NB_) {
        const int b = tile >> 9;             // /512
        const int c = tile & (C_ - 1);
        const size_t base = ((size_t)b * C_ + c) * N_ + (size_t)tid * 4;

        // Front-batched: 4 independent float4 streaming loads
        float4 xt[T_];
#pragma unroll
        for (int t = 0; t < T_; t++)
            xt[t] = __ldcs(reinterpret_cast<const float4*>(x + base + (size_t)t * strideT));

        float sums[T_] = {0.f, 0.f, 0.f, 0.f};
#pragma unroll
        for (int slot = 0; slot < 4; slot++) {
            float v = 0.f;
#pragma unroll
            for (int t = 0; t < T_; t++) {
                float xv = (slot == 0) ? xt[t].x : (slot == 1) ? xt[t].y
                         : (slot == 2) ? xt[t].z : xt[t].w;
                v = 0.5f * (v + xv);                 // v += (x - v)/TAU, TAU=2
                float s = (v >= 1.0f) ? 1.0f : 0.0f; // spike(v - V_TH)
                sums[t] += s;
                v *= (1.0f - s);                     // hard reset (detached)
            }
        }

#pragma unroll
        for (int t = 0; t < T_; t++) {
#pragma unroll
            for (int off = 16; off > 0; off >>= 1)
                sums[t] += __shfl_xor_sync(0xFFFFFFFFu, sums[t], off);
        }
        if (lane == 0) {
#pragma unroll
            for (int t = 0; t < T_; t++) red[wid][t] = sums[t];
        }
        __syncthreads();
        if (tid < T_) {
            float tot = 0.f;
#pragma unroll
            for (int w = 0; w < 8; w++) tot += red[w][tid];
            g[((tid * B_ + b) * C_) + c] = tot * (1.0f / (float)N_);
        }
        __syncthreads();                     // red[] reusable next tile
    }

    // ================= Grid barrier #1 (all NB_ blocks) =====================
    if (tid == 0) {
        __threadfence();                                   // publish g
        unsigned gen = g_bar1_gen;
        unsigned old = atomicAdd(&g_bar1_count, 1);
        if (old == NB_ - 1) {
            g_bar1_count = 0;
            __threadfence();
            g_bar1_gen = gen + 1;                          // release
        } else if (blockIdx.x < CR_) {
            while (g_bar1_gen == gen) __nanosleep(40);
        }
    }
    if (blockIdx.x >= CR_) return;            // non-MLP blocks done
    __syncthreads();
    __threadfence();                                       // acquire g

    // ================= Phase B: MLP on blocks 0..63 =========================
    const int j = blockIdx.x;                 // FC1 output column
    __shared__ float4 w1s[C_ / 4];            // 2 KB
    __shared__ float4 w2s[8 * 16];            // 2 KB: w2 rows j*8..j*8+7
    __shared__ float  hrow[TB_];
    __shared__ float  ss[4][2], sq[4][2];
    __shared__ float  ss1[4][2], sq1[4][2];

    const int grp = tid >> 6;                 // 0..3 (phase-2 column group)
    const int gt  = tid & 63;                 // phase-2 batch row
    const int gw  = (tid >> 5) & 1;
    const int jj0 = j * 8 + grp;
    const int jj1 = j * 8 + 4 + grp;

    const float b1j  = b1[j];
    const float g1j  = gamma1[j];
    const float be1j = beta1[j];
    const float b20  = b2[jj0],     b21  = b2[jj1];
    const float gm20 = gamma2[jj0], gm21 = gamma2[jj1];
    const float bt20 = beta2[jj0],  bt21 = beta2[jj1];

    // Stage w1 row j and this block's 8 w2 rows (coalesced)
    if (tid < C_ / 4) {
        w1s[tid] = reinterpret_cast<const float4*>(w1 + (size_t)j * C_)[tid];
    } else {
        const int m = tid - C_ / 4;           // 0..127
        w2s[m] = reinterpret_cast<const float4*>(w2)[(size_t)j * 128 + m];
    }
    __syncthreads();

    // ---- FC1 + BN1: h1[:, j] (g is L2-hot) ----
    {
        const int w = tid >> 5, l = tid & 31;
#pragma unroll
        for (int r = 0; r < 8; r++) {
            const int i = w * 8 + r;                       // batch row
            const float4* gr = reinterpret_cast<const float4*>(g + (size_t)i * C_);
            float acc = 0.f;
#pragma unroll
            for (int s = 0; s < 4; s++) {
                float4 a = gr[l + s * 32], wv = w1s[l + s * 32];
                acc += a.x * wv.x + a.y * wv.y + a.z * wv.z + a.w * wv.w;
            }
#pragma unroll
            for (int off = 16; off > 0; off >>= 1)
                acc += __shfl_xor_sync(0xFFFFFFFFu, acc, off);
            if (l == 0) hrow[i] = acc + b1j;
        }
    }
    __syncthreads();

    if (tid < TB_) {
        float h = hrow[tid];
        float s = h, q = h * h;
#pragma unroll
        for (int off = 16; off > 0; off >>= 1) {
            s += __shfl_xor_sync(0xFFFFFFFFu, s, off);
            q += __shfl_xor_sync(0xFFFFFFFFu, q, off);
        }
        if ((tid & 31) == 0) { ss[0][tid >> 5] = s; sq[0][tid >> 5] = q; }
    }
    __syncthreads();
    if (tid < TB_) {
        float mu  = (ss[0][0] + ss[0][1]) * (1.0f / (float)TB_);
        float ex2 = (sq[0][0] + sq[0][1]) * (1.0f / (float)TB_);
        float var = ex2 - mu * mu;
        h1[tid * CR_ + j] = (hrow[tid] - mu) * rsqrtf(var + BN_EPS) * g1j + be1j;
    }
    __syncthreads();

    // ================= Grid barrier #2 (64 MLP blocks) ======================
    if (tid == 0) {
        __threadfence();                                   // publish h1
        unsigned gen = g_bar2_gen;
        unsigned old = atomicAdd(&g_bar2_count, 1);
        if (old == CR_ - 1) {
            g_bar2_count = 0;
            __threadfence();
            g_bar2_gen = gen + 1;
        } else {
            while (g_bar2_gen == gen) __nanosleep(40);
        }
    }
    __syncthreads();
    __threadfence();                                       // acquire h1

    // ---- FC2 + BN2: out[:, j*8 .. j*8+7] (h1 L2-hot, w2 in smem) ----
    {
        const float4* hr = reinterpret_cast<const float4*>(h1 + (size_t)gt * CR_);
        const int rr0 = grp, rr1 = 4 + grp;
        float a00=0.f, a01=0.f, a02=0.f, a03=0.f;
        float a10=0.f, a11=0.f, a12=0.f, a13=0.f;
#pragma unroll
        for (int k = 0; k < CR_ / 16; k++) {
            float4 x0 = hr[k*4+0], x1 = hr[k*4+1], x2 = hr[k*4+2], x3 = hr[k*4+3];
            float4 u0 = w2s[rr0*16 + k*4+0], u1 = w2s[rr0*16 + k*4+1];
            float4 u2 = w2s[rr0*16 + k*4+2], u3 = w2s[rr0*16 + k*4+3];
            float4 v0 = w2s[rr1*16 + k*4+0], v1 = w2s[rr1*16 + k*4+1];
            float4 v2 = w2s[rr1*16 + k*4+2], v3 = w2s[rr1*16 + k*4+3];
            a00 += x0.x*u0.x + x0.y*u0.y + x0.z*u0.z + x0.w*u0.w;
            a01 += x1.x*u1.x + x1.y*u1.y + x1.z*u1.z + x1.w*u1.w;
            a02 += x2.x*u2.x + x2.y*u2.y + x2.z*u2.z + x2.w*u2.w;
            a03 += x3.x*u3.x + x3.y*u3.y + x3.z*u3.z + x3.w*u3.w;
            a10 += x0.x*v0.x + x0.y*v0.y + x0.z*v0.z + x0.w*v0.w;
            a11 += x1.x*v1.x + x1.y*v1.y + x1.z*v1.z + x1.w*v1.w;
            a12 += x2.x*v2.x + x2.y*v2.y + x2.z*v2.z + x2.w*v2.w;
            a13 += x3.x*v3.x + x3.y*v3.y + x3.z*v3.z + x3.w*v3.w;
        }
        float h0  = (a00 + a01) + (a02 + a03) + b20;
        float h1v = (a10 + a11) + (a12 + a13) + b21;

        float s0 = h0, q0 = h0 * h0, s1 = h1v, q1 = h1v * h1v;
#pragma unroll
        for (int off = 16; off > 0; off >>= 1) {
            s0 += __shfl_xor_sync(0xFFFFFFFFu, s0, off);
            q0 += __shfl_xor_sync(0xFFFFFFFFu, q0, off);
            s1 += __shfl_xor_sync(0xFFFFFFFFu, s1, off);
            q1 += __shfl_xor_sync(0xFFFFFFFFu, q1, off);
        }
        if ((gt & 31) == 0) {
            ss[grp][gw] = s0;  sq[grp][gw] = q0;
            ss1[grp][gw] = s1; sq1[grp][gw] = q1;
        }
        __syncthreads();
        {
            float mu  = (ss[grp][0] + ss[grp][1]) * (1.0f / (float)TB_);
            float ex2 = (sq[grp][0] + sq[grp][1]) * (1.0f / (float)TB_);
            float var = ex2 - mu * mu;
            out[gt * C_ + jj0] = (h0 - mu) * rsqrtf(var + BN_EPS) * gm20 + bt20;
        }
        {
            float mu  = (ss1[grp][0] + ss1[grp][1]) * (1.0f / (float)TB_);
            float ex2 = (sq1[grp][0] + sq1[grp][1]) * (1.0f / (float)TB_);
            float var = ex2 - mu * mu;
            out[gt * C_ + jj1] = (h1v - mu) * rsqrtf(var + BN_EPS) * gm21 + bt21;
        }
    }
}

// ---------------------------------------------------------------------------
extern "C" void kernel_launch(void* const* d_in, const int* in_sizes, int n_in,
                              void* d_out, int out_size) {
    const float* x      = (const float*)d_in[0];
    const float* w1     = (const float*)d_in[1];
    const float* b1     = (const float*)d_in[2];
    const float* gamma1 = (const float*)d_in[3];
    const float* beta1  = (const float*)d_in[4];
    const float* w2     = (const float*)d_in[5];
    const float* b2     = (const float*)d_in[6];
    const float* gamma2 = (const float*)d_in[7];
    const float* beta2  = (const float*)d_in[8];
    float* out = (float*)d_out;

    float* g;  cudaGetSymbolAddress((void**)&g,  g_gap);
    float* h1; cudaGetSymbolAddress((void**)&h1, g_h1);

    snn_persistent_kernel<<<NB_, 256>>>(x, w1, b1, gamma1, beta1,
                                        w2, b2, gamma2, beta2, g, h1, out);
}

// round 14
// speedup vs baseline: 1.0640x; 1.0640x over previous
#include <cuda_runtime.h>

// Problem constants
#define T_  4
#define B_  16
#define C_  512
#define N_  1024
#define CR_ 64
#define TB_ (T_ * B_)          // 64
#define BN_EPS 1e-5f

// Scratch (allocation-free rule: __device__ globals)
__device__ float g_gap[TB_ * C_];   // [64, 512]
__device__ float g_h1[TB_ * CR_];   // [64, 64]

// Software grid barrier (generation counter survives graph replays)
__device__ unsigned g_bar_count = 0;
__device__ volatile unsigned g_bar_gen = 0;

// ---------------------------------------------------------------------------
// K1: LIF over T=4 + GAP over N. One block per (b, c): 8192 blocks, 256 thr.
// (R8-proven shape: 77% DRAM, occ 89%.) Ends with the PDL trigger so the MLP
// kernel's prologue overlaps K1's tail.
// ---------------------------------------------------------------------------
__global__ void __launch_bounds__(256) lif_gap_kernel(const float* __restrict__ x,
                                                      float* __restrict__ g) {
    const int bc  = blockIdx.x;          // 0..8191
    const int b   = bc >> 9;             // /512
    const int c   = bc & (C_ - 1);
    const int tid = threadIdx.x;

    const size_t strideT = (size_t)B_ * C_ * N_;
    const size_t base = ((size_t)b * C_ + c) * N_ + (size_t)tid * 4;

    // Front-batched: 4 independent float4 streaming loads
    float4 xt[T_];
#pragma unroll
    for (int t = 0; t < T_; t++)
        xt[t] = __ldcs(reinterpret_cast<const float4*>(x + base + (size_t)t * strideT));

    float sums[T_] = {0.f, 0.f, 0.f, 0.f};
#pragma unroll
    for (int slot = 0; slot < 4; slot++) {
        float v = 0.f;
#pragma unroll
        for (int t = 0; t < T_; t++) {
            float xv = (slot == 0) ? xt[t].x : (slot == 1) ? xt[t].y
                     : (slot == 2) ? xt[t].z : xt[t].w;
            v = 0.5f * (v + xv);                 // v += (x - v)/TAU, TAU=2
            float s = (v >= 1.0f) ? 1.0f : 0.0f; // spike(v - V_TH)
            sums[t] += s;
            v *= (1.0f - s);                     // hard reset (detached)
        }
    }

    __shared__ float red[8][T_];
    const int lane = tid & 31;
    const int wid  = tid >> 5;
#pragma unroll
    for (int t = 0; t < T_; t++) {
#pragma unroll
        for (int off = 16; off > 0; off >>= 1)
            sums[t] += __shfl_xor_sync(0xFFFFFFFFu, sums[t], off);
    }
    if (lane == 0) {
#pragma unroll
        for (int t = 0; t < T_; t++) red[wid][t] = sums[t];
    }
    __syncthreads();

    if (tid < T_) {
        float tot = 0.f;
#pragma unroll
        for (int w = 0; w < 8; w++) tot += red[w][tid];
        g[((tid * B_ + b) * C_) + c] = tot * (1.0f / (float)N_);
    }

    // Allow the dependent MLP kernel to start its prologue early (PDL).
    cudaTriggerProgrammaticLaunchCompletion();
}

// ---------------------------------------------------------------------------
// K2: full MLP, fused, PDL-overlapped prologue. 64 blocks x 512 threads.
// Prologue (runs DURING K1's tail under PDL): stage w1 row j + 8 w2 rows
// into smem, load per-column scalars. cudaGridDependencySynchronize() gates
// the g-dependent work (no-op if launched without PDL).
// Phase 1: 16 warps x 4 rows, 16 front-batched loads per warp.
// Grid barrier. Phase 2: 8 groups x 64 threads, one column each.
// ---------------------------------------------------------------------------
__global__ void __launch_bounds__(512) mlp_fused_kernel(const float* __restrict__ g,
                                                        const float* __restrict__ w1,
                                                        const float* __restrict__ b1,
                                                        const float* __restrict__ gamma1,
                                                        const float* __restrict__ beta1,
                                                        const float* __restrict__ w2,
                                                        const float* __restrict__ b2,
                                                        const float* __restrict__ gamma2,
                                                        const float* __restrict__ beta2,
                                                        float* __restrict__ h1,
                                                        float* __restrict__ out) {
    const int j   = blockIdx.x;   // 0..63
    const int tid = threadIdx.x;

    __shared__ float4 w1s[C_ / 4];      // 2 KB: w1 row j
    __shared__ float4 w2s[8 * 16];      // 2 KB: w2 rows j*8..j*8+7
    __shared__ float  hrow[TB_];
    __shared__ float  ss[8][2], sq[8][2];

    // ---- Prologue: input-only loads (legal before grid sync) ----
    const float b1j  = b1[j];
    const float g1j  = gamma1[j];
    const float be1j = beta1[j];
    const int   grp  = tid >> 6;        // 0..7 (phase-2 column group)
    const int   gt   = tid & 63;        // phase-2 batch row
    const int   gw   = (tid >> 5) & 1;
    const int   jj   = j * 8 + grp;     // phase-2 output column
    const float b2j  = b2[jj];
    const float gm2  = gamma2[jj];
    const float bt2  = beta2[jj];

    if (tid < C_ / 4) {
        w1s[tid] = reinterpret_cast<const float4*>(w1 + (size_t)j * C_)[tid];
    } else if (tid < C_ / 4 + 128) {
        const int m = tid - C_ / 4;     // 0..127 -> 8 rows x 16 float4
        w2s[m] = reinterpret_cast<const float4*>(w2)[(size_t)j * 128 + m];
    }

    // ---- Wait for K1 (g ready + visible) ----
    cudaGridDependencySynchronize();

    // ---- Phase 1: h1[:, j] = BN1(g @ w1[j,:] + b1[j]) ----
    // 16 warps, 4 rows each; 16 independent loads front-batched per warp.
    const int w = tid >> 5, l = tid & 31;
    float4 abuf[16];                    // [s*4 + r]
    {
        const float4* g4 = reinterpret_cast<const float4*>(g);
#pragma unroll
        for (int s = 0; s < 4; s++)
#pragma unroll
            for (int r = 0; r < 4; r++)
                abuf[s * 4 + r] = g4[(size_t)(w * 4 + r) * (C_ / 4) + l + s * 32];
    }
    __syncthreads();                    // w1s/w2s ready (abuf loads in flight)

    {
        float acc[4] = {0.f, 0.f, 0.f, 0.f};
#pragma unroll
        for (int s = 0; s < 4; s++) {
            float4 wv = w1s[l + s * 32];
#pragma unroll
            for (int r = 0; r < 4; r++) {
                float4 a = abuf[s * 4 + r];
                acc[r] += a.x * wv.x + a.y * wv.y + a.z * wv.z + a.w * wv.w;
            }
        }
#pragma unroll
        for (int off = 16; off > 0; off >>= 1)
#pragma unroll
            for (int r = 0; r < 4; r++)
                acc[r] += __shfl_xor_sync(0xFFFFFFFFu, acc[r], off);
        if (l == 0) {
#pragma unroll
            for (int r = 0; r < 4; r++) hrow[w * 4 + r] = acc[r] + b1j;
        }
    }
    __syncthreads();

    // BN1 column stats (64 values, 2 warps)
    if (tid < TB_) {
        float h = hrow[tid];
        float s = h, q = h * h;
#pragma unroll
        for (int off = 16; off > 0; off >>= 1) {
            s += __shfl_xor_sync(0xFFFFFFFFu, s, off);
            q += __shfl_xor_sync(0xFFFFFFFFu, q, off);
        }
        if ((tid & 31) == 0) { ss[0][tid >> 5] = s; sq[0][tid >> 5] = q; }
    }
    __syncthreads();
    if (tid < TB_) {
        float mu  = (ss[0][0] + ss[0][1]) * (1.0f / (float)TB_);
        float ex2 = (sq[0][0] + sq[0][1]) * (1.0f / (float)TB_);
        float var = ex2 - mu * mu;
        h1[tid * CR_ + j] = (hrow[tid] - mu) * rsqrtf(var + BN_EPS) * g1j + be1j;
    }
    __syncthreads();

    // ---- Grid barrier (64 co-resident blocks) ----
    if (tid == 0) {
        __threadfence();                               // publish h1
        unsigned gen = g_bar_gen;
        unsigned old = atomicAdd(&g_bar_count, 1);
        if (old == (unsigned)(gridDim.x - 1)) {
            g_bar_count = 0;
            __threadfence();
            g_bar_gen = gen + 1;                       // release
        } else {
            while (g_bar_gen == gen) __nanosleep(40);
        }
    }
    __syncthreads();
    __threadfence();                                   // acquire h1

    // ---- Phase 2: out[:, jj] for the 8 columns of this block ----
    {
        const float4* hr = reinterpret_cast<const float4*>(h1 + (size_t)gt * CR_);
        float a0 = 0.f, a1 = 0.f, a2 = 0.f, a3 = 0.f;
#pragma unroll
        for (int k = 0; k < CR_ / 16; k++) {
            float4 x0 = hr[k*4+0], x1 = hr[k*4+1], x2 = hr[k*4+2], x3 = hr[k*4+3];
            float4 u0 = w2s[grp*16 + k*4+0], u1 = w2s[grp*16 + k*4+1];
            float4 u2 = w2s[grp*16 + k*4+2], u3 = w2s[grp*16 + k*4+3];
            a0 += x0.x*u0.x + x0.y*u0.y + x0.z*u0.z + x0.w*u0.w;
            a1 += x1.x*u1.x + x1.y*u1.y + x1.z*u1.z + x1.w*u1.w;
            a2 += x2.x*u2.x + x2.y*u2.y + x2.z*u2.z + x2.w*u2.w;
            a3 += x3.x*u3.x + x3.y*u3.y + x3.z*u3.z + x3.w*u3.w;
        }
        float h = (a0 + a1) + (a2 + a3) + b2j;

        float s = h, q = h * h;
#pragma unroll
        for (int off = 16; off > 0; off >>= 1) {
            s += __shfl_xor_sync(0xFFFFFFFFu, s, off);
            q += __shfl_xor_sync(0xFFFFFFFFu, q, off);
        }
        if ((gt & 31) == 0) { ss[grp][gw] = s; sq[grp][gw] = q; }
        __syncthreads();
        float mu  = (ss[grp][0] + ss[grp][1]) * (1.0f / (float)TB_);
        float ex2 = (sq[grp][0] + sq[grp][1]) * (1.0f / (float)TB_);
        float var = ex2 - mu * mu;
        out[gt * C_ + jj] = (h - mu) * rsqrtf(var + BN_EPS) * gm2 + bt2;
    }
}

// ---------------------------------------------------------------------------
extern "C" void kernel_launch(void* const* d_in, const int* in_sizes, int n_in,
                              void* d_out, int out_size) {
    const float* x      = (const float*)d_in[0];
    const float* w1     = (const float*)d_in[1];
    const float* b1     = (const float*)d_in[2];
    const float* gamma1 = (const float*)d_in[3];
    const float* beta1  = (const float*)d_in[4];
    const float* w2     = (const float*)d_in[5];
    const float* b2     = (const float*)d_in[6];
    const float* gamma2 = (const float*)d_in[7];
    const float* beta2  = (const float*)d_in[8];
    float* out = (float*)d_out;

    float* g;  cudaGetSymbolAddress((void**)&g,  g_gap);
    float* h1; cudaGetSymbolAddress((void**)&h1, g_h1);

    lif_gap_kernel<<<B_ * C_, 256>>>(x, g);

    // PDL launch: MLP prologue overlaps K1's tail; grid-sync gates g reads.
    // If PDL launch is rejected in this environment, fall back to a plain
    // stream-ordered launch of the SAME kernel (grid-sync degrades to no-op).
    cudaLaunchConfig_t cfg = {};
    cfg.gridDim  = dim3(CR_, 1, 1);
    cfg.blockDim = dim3(512, 1, 1);
    cfg.dynamicSmemBytes = 0;
    cfg.stream = 0;
    cudaLaunchAttribute attrs[1];
    attrs[0].id = cudaLaunchAttributeProgrammaticStreamSerialization;
    attrs[0].val.programmaticStreamSerializationAllowed = 1;
    cfg.attrs = attrs;
    cfg.numAttrs = 1;
    cudaError_t err = cudaLaunchKernelEx(&cfg, mlp_fused_kernel,
                                         (const float*)g, w1, b1, gamma1, beta1,
                                         w2, b2, gamma2, beta2, h1, out);
    if (err != cudaSuccess) {
        (void)cudaGetLastError();       // clear sticky error, then plain launch
        mlp_fused_kernel<<<CR_, 512>>>((const float*)g, w1, b1, gamma1, beta1,
                                       w2, b2, gamma2, beta2, h1, out);
    }
}